// round 4
// baseline (speedup 1.0000x reference)
#include <cuda_runtime.h>
#include <math.h>

#define Bn 2
#define Nn 1024
#define Dn 64
#define SCHUNKS 8           // s-dimension split for msg_agg
#define TT 64               // t-tile per block in msg_agg
#define SC (Nn / SCHUNKS)   // 128 s per block
#define SA_STRIDE 68        // padded [s][t] stride, float4-aligned
#define NTILES (Nn / TT)    // 16

typedef unsigned long long u64t;

// -------- scratch (no malloc allowed) --------
__device__ float g_ps[Bn * Nn * Dn];
__device__ float g_ptb[Bn * Nn * Dn];
__device__ float g_hpart[SCHUNKS * Bn * Nn * Dn];
__device__ int   g_cnt[Bn * NTILES];     // zero-init; self-resetting

// ---------- packed f32x2 helpers ----------
__device__ __forceinline__ u64t pack2(float lo, float hi) {
    u64t r;
    asm("mov.b64 %0, {%1, %2};" : "=l"(r) : "f"(lo), "f"(hi));
    return r;
}
__device__ __forceinline__ void unpack2(u64t v, float& lo, float& hi) {
    asm("mov.b64 {%0, %1}, %2;" : "=f"(lo), "=f"(hi) : "l"(v));
}
__device__ __forceinline__ u64t add2(u64t a, u64t b) {
    u64t d;
    asm("add.rn.f32x2 %0, %1, %2;" : "=l"(d) : "l"(a), "l"(b));
    return d;
}
__device__ __forceinline__ u64t fma2(u64t a, u64t b, u64t c) {
    u64t d;
    asm("fma.rn.f32x2 %0, %1, %2, %3;" : "=l"(d) : "l"(a), "l"(b), "l"(c));
    return d;
}
__device__ __forceinline__ u64t relu2(u64t x) {
    u64t r;
    asm("{\n\t"
        ".reg .f32 lo, hi;\n\t"
        "mov.b64 {lo, hi}, %1;\n\t"
        "max.f32 lo, lo, 0f00000000;\n\t"
        "max.f32 hi, hi, 0f00000000;\n\t"
        "mov.b64 %0, {lo, hi};\n\t"
        "}" : "=l"(r) : "l"(x));
    return r;
}

// ============================================================
// K1: gumbel softmax, one block per row, float4 I/O, tiny smem
// ============================================================
__global__ void __launch_bounds__(256) gumbel_softmax_kernel(
    const float* __restrict__ u, const float* __restrict__ el,
    float* __restrict__ A)
{
    __shared__ float redm[8];
    __shared__ float reds[8];
    int t = blockIdx.x;
    int tid = threadIdx.x;

    float4 u4 = ((const float4*)(u + t * Nn))[tid];
    float4 e4 = ((const float4*)(el + t * Nn))[tid];
    int s0 = tid * 4;

    float v[4];
    {
        float uu[4] = {u4.x, u4.y, u4.z, u4.w};
        float ee[4] = {e4.x, e4.y, e4.z, e4.w};
#pragma unroll
        for (int i = 0; i < 4; i++) {
            float g = -__logf(-__logf(uu[i] + 1e-9f) + 1e-9f);
            float m = (s0 + i == t) ? -1e9f : ee[i];
            v[i] = (m + g) * 2.0f;   // / tau, tau = 0.5
        }
    }
    float mx = fmaxf(fmaxf(v[0], v[1]), fmaxf(v[2], v[3]));
#pragma unroll
    for (int o = 16; o; o >>= 1) mx = fmaxf(mx, __shfl_xor_sync(0xffffffffu, mx, o));
    if ((tid & 31) == 0) redm[tid >> 5] = mx;
    __syncthreads();
    float bm = redm[0];
#pragma unroll
    for (int i = 1; i < 8; i++) bm = fmaxf(bm, redm[i]);

    float sum = 0.f;
#pragma unroll
    for (int i = 0; i < 4; i++) { v[i] = __expf(v[i] - bm); sum += v[i]; }
#pragma unroll
    for (int o = 16; o; o >>= 1) sum += __shfl_xor_sync(0xffffffffu, sum, o);
    if ((tid & 31) == 0) reds[tid >> 5] = sum;
    __syncthreads();
    float bs = reds[0];
#pragma unroll
    for (int i = 1; i < 8; i++) bs += reds[i];
    float inv = 1.0f / bs;

    float4 o4 = make_float4(v[0] * inv, v[1] * inv, v[2] * inv, v[3] * inv);
    ((float4*)(A + t * Nn))[tid] = o4;
}

// ============================================================
// K2: chained in-smem GEMMs: proj = es@Wp+bp;  ps = proj@W1[:64],
//     ptb = proj@W1[64:]+b1.  128 blocks x 16 rows.
// ============================================================
__global__ void __launch_bounds__(256) pspt_kernel(
    const float* __restrict__ es, const float* __restrict__ Wp,
    const float* __restrict__ bp, const float* __restrict__ W1,
    const float* __restrict__ b1)
{
    __shared__ __align__(16) float sW1[128 * 64];  // 32 KB
    __shared__ __align__(16) float sWp[64 * 64];   // 16 KB
    __shared__ __align__(16) float sE[16 * 64];
    __shared__ __align__(16) float sPr[16 * 64];
    int tid = threadIdx.x;
    int row0 = blockIdx.x * 16;

    for (int i = tid; i < 8192; i += 256) sW1[i] = W1[i];
    for (int i = tid; i < 4096; i += 256) sWp[i] = Wp[i];
    for (int i = tid; i < 1024; i += 256) sE[i] = es[row0 * 64 + i];
    __syncthreads();

    int r = tid >> 4;
    int q = (tid & 15) << 2;
    {
        float4 acc = *(const float4*)(bp + q);
        const float* er = sE + r * 64;
#pragma unroll
        for (int k = 0; k < 64; k++) {
            float e = er[k];
            float4 w = *(const float4*)(sWp + k * 64 + q);
            acc.x = fmaf(e, w.x, acc.x);
            acc.y = fmaf(e, w.y, acc.y);
            acc.z = fmaf(e, w.z, acc.z);
            acc.w = fmaf(e, w.w, acc.w);
        }
        *(float4*)(sPr + r * 64 + q) = acc;
    }
    __syncthreads();
    {
        float4 aps = make_float4(0.f, 0.f, 0.f, 0.f);
        float4 apt = *(const float4*)(b1 + q);
        const float* pr = sPr + r * 64;
#pragma unroll
        for (int k = 0; k < 64; k++) {
            float p = pr[k];
            float4 wa = *(const float4*)(sW1 + k * 64 + q);
            float4 wb = *(const float4*)(sW1 + (64 + k) * 64 + q);
            aps.x = fmaf(p, wa.x, aps.x);
            aps.y = fmaf(p, wa.y, aps.y);
            aps.z = fmaf(p, wa.z, aps.z);
            aps.w = fmaf(p, wa.w, aps.w);
            apt.x = fmaf(p, wb.x, apt.x);
            apt.y = fmaf(p, wb.y, apt.y);
            apt.z = fmaf(p, wb.z, apt.z);
            apt.w = fmaf(p, wb.w, apt.w);
        }
        *(float4*)(g_ps  + (row0 + r) * 64 + q) = aps;
        *(float4*)(g_ptb + (row0 + r) * 64 + q) = apt;
    }
}

// ============================================================
// K3 (hot): hpart[c,b,t,:] = sum_{s in chunk c} A[t,s]*relu(ps[b,s,:]+ptb[b,t,:])
// + last-block-per-(b,ttile) epilogue: hbar = sum_c hpart;
//   next_state = es + hbar @ W2 + b2
// grid (SCHUNKS, NTILES, Bn) = 256 blocks, 256 threads, one wave.
// ============================================================
__global__ void __launch_bounds__(256, 3) msg_agg_kernel(
    const float* __restrict__ A, const float* __restrict__ es,
    const float* __restrict__ W2, const float* __restrict__ b2,
    float* __restrict__ ns)
{
    __shared__ __align__(16) float sP[SC * 64];          // 32 KB (reused as sH 16KB)
    __shared__ __align__(16) float sA[SC * SA_STRIDE];   // 34.8 KB (reused as sW2 16KB)
    __shared__ int sLast;
    int b  = blockIdx.z;
    int t0 = blockIdx.y * TT;
    int s0 = blockIdx.x * SC;
    int tid = threadIdx.x;

    {
        const float4* gp = (const float4*)(g_ps + (b * Nn + s0) * Dn);
        float4* sp4 = (float4*)sP;
#pragma unroll
        for (int i = 0; i < (SC * 16) / 256; i++)
            sp4[tid + i * 256] = gp[tid + i * 256];
#pragma unroll 8
        for (int k = 0; k < (TT * SC) / 256; k++) {
            int i = tid + k * 256;
            int sl = i & (SC - 1);
            int tl = i >> 7;           // / SC(=128)
            sA[sl * SA_STRIDE + tl] = A[(t0 + tl) * Nn + s0 + sl];
        }
    }
    __syncthreads();

    int q4 = (tid & 15) << 2;
    int tg = tid >> 4;
    int ta = t0 + tg * 4;

    u64t c[8];
#pragma unroll
    for (int i = 0; i < 4; i++) {
        float4 cv = *(const float4*)(g_ptb + (b * Nn + ta + i) * Dn + q4);
        c[2 * i]     = pack2(cv.x, cv.y);
        c[2 * i + 1] = pack2(cv.z, cv.w);
    }
    u64t acc[8];
#pragma unroll
    for (int i = 0; i < 8; i++) acc[i] = 0;

    const float4* pbase = ((const float4*)sP) + (tid & 15);
    const float4* abase = ((const float4*)sA) + tg;

#pragma unroll 8
    for (int s = 0; s < SC; s++) {
        float4 p  = pbase[s * 16];
        float4 av = abase[s * (SA_STRIDE / 4)];
        u64t pa = pack2(p.x, p.y);
        u64t pb = pack2(p.z, p.w);
        u64t a0 = pack2(av.x, av.x);
        u64t a1 = pack2(av.y, av.y);
        u64t a2 = pack2(av.z, av.z);
        u64t a3 = pack2(av.w, av.w);
        acc[0] = fma2(a0, relu2(add2(pa, c[0])), acc[0]);
        acc[1] = fma2(a0, relu2(add2(pb, c[1])), acc[1]);
        acc[2] = fma2(a1, relu2(add2(pa, c[2])), acc[2]);
        acc[3] = fma2(a1, relu2(add2(pb, c[3])), acc[3]);
        acc[4] = fma2(a2, relu2(add2(pa, c[4])), acc[4]);
        acc[5] = fma2(a2, relu2(add2(pb, c[5])), acc[5]);
        acc[6] = fma2(a3, relu2(add2(pa, c[6])), acc[6]);
        acc[7] = fma2(a3, relu2(add2(pb, c[7])), acc[7]);
    }

    {
        int cidx = blockIdx.x;
        float* hp = g_hpart + ((size_t)(cidx * Bn + b) * Nn + ta) * Dn + q4;
#pragma unroll
        for (int i = 0; i < 4; i++) {
            float4 o;
            unpack2(acc[2 * i],     o.x, o.y);
            unpack2(acc[2 * i + 1], o.z, o.w);
            *(float4*)(hp + (size_t)i * Dn) = o;
        }
    }

    // ---- last-block epilogue (fence-reduction pattern) ----
    int gid = b * NTILES + blockIdx.y;
    __threadfence();
    __syncthreads();
    if (tid == 0) sLast = (atomicAdd(&g_cnt[gid], 1) == SCHUNKS - 1);
    __syncthreads();
    if (!sLast) return;
    __threadfence();

    float* sH  = sP;   // 64 x 64
    float* sW2 = sA;   // 64 x 64
    {
        float4* w4 = (float4*)sW2;
        const float4* g4 = (const float4*)W2;
#pragma unroll
        for (int i = 0; i < 4; i++) w4[tid + i * 256] = g4[tid + i * 256];
    }
#pragma unroll
    for (int i = 0; i < 4; i++) {
        int idx = tid + i * 256;            // float4 index in [64 rows][16]
        int row = idx >> 4;
        int f4c = idx & 15;
        float4 a = make_float4(0.f, 0.f, 0.f, 0.f);
#pragma unroll
        for (int cc = 0; cc < SCHUNKS; cc++) {
            float4 v = ((const float4*)g_hpart)[
                ((size_t)(cc * Bn + b) * Nn + t0 + row) * 16 + f4c];
            a.x += v.x; a.y += v.y; a.z += v.z; a.w += v.w;
        }
        ((float4*)sH)[idx] = a;
    }
    __syncthreads();

    int q = (tid & 15) << 2;
#pragma unroll
    for (int g = 0; g < 4; g++) {
        int r = (tid >> 4) + g * 16;        // 0..63
        float4 acco = *(const float4*)(b2 + q);
        const float* hr = sH + r * 64;
#pragma unroll
        for (int k = 0; k < 64; k++) {
            float h = hr[k];
            float4 w = *(const float4*)(sW2 + k * 64 + q);
            acco.x = fmaf(h, w.x, acco.x);
            acco.y = fmaf(h, w.y, acco.y);
            acco.z = fmaf(h, w.z, acco.z);
            acco.w = fmaf(h, w.w, acco.w);
        }
        float4 e = *(const float4*)(es + ((size_t)(b * Nn + t0 + r)) * 64 + q);
        acco.x += e.x; acco.y += e.y; acco.z += e.z; acco.w += e.w;
        *(float4*)(ns + ((size_t)(b * Nn + t0 + r)) * 64 + q) = acco;
    }
    if (tid == 0) g_cnt[gid] = 0;   // reset for next graph replay
}

// ============================================================
extern "C" void kernel_launch(void* const* d_in, const int* in_sizes, int n_in,
                              void* d_out, int out_size)
{
    const float* es = (const float*)d_in[0];
    const float* u  = (const float*)d_in[1];
    const float* Wp = (const float*)d_in[2];
    const float* bp = (const float*)d_in[3];
    const float* el = (const float*)d_in[4];
    const float* W1 = (const float*)d_in[5];
    const float* b1 = (const float*)d_in[6];
    const float* W2 = (const float*)d_in[7];
    const float* b2 = (const float*)d_in[8];

    float* outNS = (float*)d_out;                 // next_state [B,N,D]
    float* outA  = outNS + Bn * Nn * Dn;          // A [N,N]

    gumbel_softmax_kernel<<<Nn, 256>>>(u, el, outA);
    pspt_kernel<<<(Bn * Nn) / 16, 256>>>(es, Wp, bp, W1, b1);
    msg_agg_kernel<<<dim3(SCHUNKS, NTILES, Bn), 256>>>(outA, es, W2, b2, outNS);
}

// round 5
// speedup vs baseline: 1.4517x; 1.4517x over previous
#include <cuda_runtime.h>
#include <math.h>

#define Bn 2
#define Nn 1024
#define Dn 64
#define SCHUNKS 16          // s-dimension split for msg_agg
#define TT 64               // t-tile per block in msg_agg
#define SC (Nn / SCHUNKS)   // 64 s per block
#define SA_STRIDE 68        // padded [s][t] stride, float4-aligned

typedef unsigned long long u64t;

// -------- scratch (no malloc allowed) --------
__device__ float g_ps[Bn * Nn * Dn];
__device__ float g_ptb[Bn * Nn * Dn];
__device__ float g_hpart[SCHUNKS * Bn * Nn * Dn];

// ---------- packed f32x2 helpers ----------
__device__ __forceinline__ u64t pack2(float lo, float hi) {
    u64t r;
    asm("mov.b64 %0, {%1, %2};" : "=l"(r) : "f"(lo), "f"(hi));
    return r;
}
__device__ __forceinline__ void unpack2(u64t v, float& lo, float& hi) {
    asm("mov.b64 {%0, %1}, %2;" : "=f"(lo), "=f"(hi) : "l"(v));
}
__device__ __forceinline__ u64t add2(u64t a, u64t b) {
    u64t d;
    asm("add.rn.f32x2 %0, %1, %2;" : "=l"(d) : "l"(a), "l"(b));
    return d;
}
__device__ __forceinline__ u64t fma2(u64t a, u64t b, u64t c) {
    u64t d;
    asm("fma.rn.f32x2 %0, %1, %2, %3;" : "=l"(d) : "l"(a), "l"(b), "l"(c));
    return d;
}
__device__ __forceinline__ u64t relu2(u64t x) {
    u64t r;
    asm("{\n\t"
        ".reg .f32 lo, hi;\n\t"
        "mov.b64 {lo, hi}, %1;\n\t"
        "max.f32 lo, lo, 0f00000000;\n\t"
        "max.f32 hi, hi, 0f00000000;\n\t"
        "mov.b64 %0, {lo, hi};\n\t"
        "}" : "=l"(r) : "l"(x));
    return r;
}

// ============================================================
// K1: gumbel softmax, 2 rows per block (ILP), float4 I/O
// ============================================================
__global__ void __launch_bounds__(256) gumbel_softmax_kernel(
    const float* __restrict__ u, const float* __restrict__ el,
    float* __restrict__ A)
{
    __shared__ float redm[2][8];
    __shared__ float reds[2][8];
    int t0 = blockIdx.x * 2;
    int tid = threadIdx.x;
    int s0 = tid * 4;

    float4 u4a = ((const float4*)(u + (size_t)t0 * Nn))[tid];
    float4 u4b = ((const float4*)(u + (size_t)(t0 + 1) * Nn))[tid];
    float4 e4a = ((const float4*)(el + (size_t)t0 * Nn))[tid];
    float4 e4b = ((const float4*)(el + (size_t)(t0 + 1) * Nn))[tid];

    float va[4], vb[4];
    {
        float ua[4] = {u4a.x, u4a.y, u4a.z, u4a.w};
        float ub[4] = {u4b.x, u4b.y, u4b.z, u4b.w};
        float ea[4] = {e4a.x, e4a.y, e4a.z, e4a.w};
        float eb[4] = {e4b.x, e4b.y, e4b.z, e4b.w};
#pragma unroll
        for (int i = 0; i < 4; i++) {
            float ga = -__logf(-__logf(ua[i] + 1e-9f) + 1e-9f);
            float gb = -__logf(-__logf(ub[i] + 1e-9f) + 1e-9f);
            float ma = (s0 + i == t0)     ? -1e9f : ea[i];
            float mb = (s0 + i == t0 + 1) ? -1e9f : eb[i];
            va[i] = (ma + ga) * 2.0f;   // / tau, tau = 0.5
            vb[i] = (mb + gb) * 2.0f;
        }
    }
    float mxa = fmaxf(fmaxf(va[0], va[1]), fmaxf(va[2], va[3]));
    float mxb = fmaxf(fmaxf(vb[0], vb[1]), fmaxf(vb[2], vb[3]));
#pragma unroll
    for (int o = 16; o; o >>= 1) {
        mxa = fmaxf(mxa, __shfl_xor_sync(0xffffffffu, mxa, o));
        mxb = fmaxf(mxb, __shfl_xor_sync(0xffffffffu, mxb, o));
    }
    if ((tid & 31) == 0) { redm[0][tid >> 5] = mxa; redm[1][tid >> 5] = mxb; }
    __syncthreads();
    float bma = redm[0][0], bmb = redm[1][0];
#pragma unroll
    for (int i = 1; i < 8; i++) {
        bma = fmaxf(bma, redm[0][i]);
        bmb = fmaxf(bmb, redm[1][i]);
    }

    float suma = 0.f, sumb = 0.f;
#pragma unroll
    for (int i = 0; i < 4; i++) {
        va[i] = __expf(va[i] - bma); suma += va[i];
        vb[i] = __expf(vb[i] - bmb); sumb += vb[i];
    }
#pragma unroll
    for (int o = 16; o; o >>= 1) {
        suma += __shfl_xor_sync(0xffffffffu, suma, o);
        sumb += __shfl_xor_sync(0xffffffffu, sumb, o);
    }
    if ((tid & 31) == 0) { reds[0][tid >> 5] = suma; reds[1][tid >> 5] = sumb; }
    __syncthreads();
    float bsa = reds[0][0], bsb = reds[1][0];
#pragma unroll
    for (int i = 1; i < 8; i++) { bsa += reds[0][i]; bsb += reds[1][i]; }
    float inva = 1.0f / bsa, invb = 1.0f / bsb;

    ((float4*)(A + (size_t)t0 * Nn))[tid] =
        make_float4(va[0] * inva, va[1] * inva, va[2] * inva, va[3] * inva);
    ((float4*)(A + (size_t)(t0 + 1) * Nn))[tid] =
        make_float4(vb[0] * invb, vb[1] * invb, vb[2] * invb, vb[3] * invb);
}

// ============================================================
// K2: chained in-smem GEMMs: proj = es@Wp+bp;  ps = proj@W1[:64],
//     ptb = proj@W1[64:]+b1.  128 blocks x 16 rows.
// ============================================================
__global__ void __launch_bounds__(256) pspt_kernel(
    const float* __restrict__ es, const float* __restrict__ Wp,
    const float* __restrict__ bp, const float* __restrict__ W1,
    const float* __restrict__ b1)
{
    __shared__ __align__(16) float sW1[128 * 64];  // 32 KB
    __shared__ __align__(16) float sWp[64 * 64];   // 16 KB
    __shared__ __align__(16) float sE[16 * 64];
    __shared__ __align__(16) float sPr[16 * 64];
    int tid = threadIdx.x;
    int row0 = blockIdx.x * 16;

    for (int i = tid; i < 8192; i += 256) sW1[i] = W1[i];
    for (int i = tid; i < 4096; i += 256) sWp[i] = Wp[i];
    for (int i = tid; i < 1024; i += 256) sE[i] = es[row0 * 64 + i];
    __syncthreads();

    int r = tid >> 4;
    int q = (tid & 15) << 2;
    {
        float4 acc = *(const float4*)(bp + q);
        const float* er = sE + r * 64;
#pragma unroll
        for (int k = 0; k < 64; k++) {
            float e = er[k];
            float4 w = *(const float4*)(sWp + k * 64 + q);
            acc.x = fmaf(e, w.x, acc.x);
            acc.y = fmaf(e, w.y, acc.y);
            acc.z = fmaf(e, w.z, acc.z);
            acc.w = fmaf(e, w.w, acc.w);
        }
        *(float4*)(sPr + r * 64 + q) = acc;
    }
    __syncthreads();
    {
        float4 aps = make_float4(0.f, 0.f, 0.f, 0.f);
        float4 apt = *(const float4*)(b1 + q);
        const float* pr = sPr + r * 64;
#pragma unroll
        for (int k = 0; k < 64; k++) {
            float p = pr[k];
            float4 wa = *(const float4*)(sW1 + k * 64 + q);
            float4 wb = *(const float4*)(sW1 + (64 + k) * 64 + q);
            aps.x = fmaf(p, wa.x, aps.x);
            aps.y = fmaf(p, wa.y, aps.y);
            aps.z = fmaf(p, wa.z, aps.z);
            aps.w = fmaf(p, wa.w, aps.w);
            apt.x = fmaf(p, wb.x, apt.x);
            apt.y = fmaf(p, wb.y, apt.y);
            apt.z = fmaf(p, wb.z, apt.z);
            apt.w = fmaf(p, wb.w, apt.w);
        }
        *(float4*)(g_ps  + (row0 + r) * 64 + q) = aps;
        *(float4*)(g_ptb + (row0 + r) * 64 + q) = apt;
    }
}

// ============================================================
// K3 (hot): hpart[c,b,t,:] = sum_{s in chunk c} A[t,s]*relu(ps[b,s,:]+ptb[b,t,:])
// grid (SCHUNKS, Nn/TT, Bn), 256 threads
// ============================================================
__global__ void __launch_bounds__(256, 4) msg_agg_kernel(const float* __restrict__ A)
{
    __shared__ __align__(16) float sP[SC * 64];          // 16 KB [s][d]
    __shared__ __align__(16) float sA[SC * SA_STRIDE];   // 17.4 KB [s][t], padded
    int b  = blockIdx.z;
    int t0 = blockIdx.y * TT;
    int s0 = blockIdx.x * SC;
    int tid = threadIdx.x;

    {
        const float4* gp = (const float4*)(g_ps + (b * Nn + s0) * Dn);
        float4* sp4 = (float4*)sP;
#pragma unroll
        for (int i = 0; i < (SC * 16) / 256; i++)
            sp4[tid + i * 256] = gp[tid + i * 256];
#pragma unroll
        for (int k = 0; k < (TT * SC) / 256; k++) {
            int i = tid + k * 256;
            int sl = i & (SC - 1);
            int tl = i >> 6;           // / SC(=64)
            sA[sl * SA_STRIDE + tl] = A[(t0 + tl) * Nn + s0 + sl];
        }
    }
    __syncthreads();

    int q4 = (tid & 15) << 2;
    int tg = tid >> 4;
    int ta = t0 + tg * 4;

    u64t c[8];
#pragma unroll
    for (int i = 0; i < 4; i++) {
        float4 cv = *(const float4*)(g_ptb + (b * Nn + ta + i) * Dn + q4);
        c[2 * i]     = pack2(cv.x, cv.y);
        c[2 * i + 1] = pack2(cv.z, cv.w);
    }
    u64t acc[8];
#pragma unroll
    for (int i = 0; i < 8; i++) acc[i] = 0;

    const float4* pbase = ((const float4*)sP) + (tid & 15);
    const float4* abase = ((const float4*)sA) + tg;

#pragma unroll 8
    for (int s = 0; s < SC; s++) {
        float4 p  = pbase[s * 16];
        float4 av = abase[s * (SA_STRIDE / 4)];
        u64t pa = pack2(p.x, p.y);
        u64t pb = pack2(p.z, p.w);
        u64t a0 = pack2(av.x, av.x);
        u64t a1 = pack2(av.y, av.y);
        u64t a2 = pack2(av.z, av.z);
        u64t a3 = pack2(av.w, av.w);
        acc[0] = fma2(a0, relu2(add2(pa, c[0])), acc[0]);
        acc[1] = fma2(a0, relu2(add2(pb, c[1])), acc[1]);
        acc[2] = fma2(a1, relu2(add2(pa, c[2])), acc[2]);
        acc[3] = fma2(a1, relu2(add2(pb, c[3])), acc[3]);
        acc[4] = fma2(a2, relu2(add2(pa, c[4])), acc[4]);
        acc[5] = fma2(a2, relu2(add2(pb, c[5])), acc[5]);
        acc[6] = fma2(a3, relu2(add2(pa, c[6])), acc[6]);
        acc[7] = fma2(a3, relu2(add2(pb, c[7])), acc[7]);
    }

    int cidx = blockIdx.x;
    float* hp = g_hpart + ((size_t)(cidx * Bn + b) * Nn + ta) * Dn + q4;
#pragma unroll
    for (int i = 0; i < 4; i++) {
        float4 o;
        unpack2(acc[2 * i],     o.x, o.y);
        unpack2(acc[2 * i + 1], o.z, o.w);
        *(float4*)(hp + (size_t)i * Dn) = o;
    }
}

// ============================================================
// K4: hbar = sum_c hpart;  next_state = es + hbar @ W2 + b2
// ============================================================
__global__ void __launch_bounds__(256) out_kernel(
    const float* __restrict__ es, const float* __restrict__ W2,
    const float* __restrict__ b2, float* __restrict__ ns)
{
    __shared__ __align__(16) float sW[64 * 64];
    __shared__ __align__(16) float sH[16 * 64];
    int tid = threadIdx.x;
    int row0 = blockIdx.x * 16;    // global row in [0, B*N)

    for (int i = tid; i < 4096; i += 256) sW[i] = W2[i];
    {
        int r  = tid >> 4;
        int f4 = tid & 15;
        size_t base = ((size_t)(row0 + r)) * 16 + f4;
        float4 acc = make_float4(0.f, 0.f, 0.f, 0.f);
#pragma unroll
        for (int cc = 0; cc < SCHUNKS; cc++) {
            float4 v = ((const float4*)g_hpart)[(size_t)cc * (Bn * Nn * 16) + base];
            acc.x += v.x; acc.y += v.y; acc.z += v.z; acc.w += v.w;
        }
        ((float4*)sH)[tid] = acc;
    }
    __syncthreads();

    int r = tid >> 4;
    int q = (tid & 15) << 2;
    float4 acc = *(const float4*)(b2 + q);
    const float* hr = sH + r * 64;
#pragma unroll
    for (int k = 0; k < 64; k++) {
        float h = hr[k];
        float4 w = *(const float4*)(sW + k * 64 + q);
        acc.x = fmaf(h, w.x, acc.x);
        acc.y = fmaf(h, w.y, acc.y);
        acc.z = fmaf(h, w.z, acc.z);
        acc.w = fmaf(h, w.w, acc.w);
    }
    float4 e = *(const float4*)(es + (row0 + r) * 64 + q);
    acc.x += e.x; acc.y += e.y; acc.z += e.z; acc.w += e.w;
    *(float4*)(ns + (row0 + r) * 64 + q) = acc;
}

// ============================================================
extern "C" void kernel_launch(void* const* d_in, const int* in_sizes, int n_in,
                              void* d_out, int out_size)
{
    const float* es = (const float*)d_in[0];
    const float* u  = (const float*)d_in[1];
    const float* Wp = (const float*)d_in[2];
    const float* bp = (const float*)d_in[3];
    const float* el = (const float*)d_in[4];
    const float* W1 = (const float*)d_in[5];
    const float* b1 = (const float*)d_in[6];
    const float* W2 = (const float*)d_in[7];
    const float* b2 = (const float*)d_in[8];

    float* outNS = (float*)d_out;                 // next_state [B,N,D]
    float* outA  = outNS + Bn * Nn * Dn;          // A [N,N]

    gumbel_softmax_kernel<<<Nn / 2, 256>>>(u, el, outA);
    pspt_kernel<<<(Bn * Nn) / 16, 256>>>(es, Wp, bp, W1, b1);
    msg_agg_kernel<<<dim3(SCHUNKS, Nn / TT, Bn), 256>>>(outA);
    out_kernel<<<(Bn * Nn) / 16, 256>>>(es, W2, b2, outNS);
}

// round 6
// speedup vs baseline: 1.5313x; 1.0548x over previous
#include <cuda_runtime.h>
#include <math.h>

#define Bn 2
#define Nn 1024
#define Dn 64
#define SCHUNKS 16          // s-dimension split for msg_agg
#define TT 64               // t-tile per block in msg_agg
#define SC (Nn / SCHUNKS)   // 64 s per block
#define SA_STRIDE 68        // padded [s][t] stride, float4-aligned

typedef unsigned long long u64t;

// -------- scratch (no malloc allowed) --------
__device__ float g_ps[Bn * Nn * Dn];
__device__ float g_ptb[Bn * Nn * Dn];
__device__ float g_hpart[SCHUNKS * Bn * Nn * Dn];

// ---------- packed f32x2 helpers ----------
__device__ __forceinline__ u64t pack2(float lo, float hi) {
    u64t r;
    asm("mov.b64 %0, {%1, %2};" : "=l"(r) : "f"(lo), "f"(hi));
    return r;
}
__device__ __forceinline__ void unpack2(u64t v, float& lo, float& hi) {
    asm("mov.b64 {%0, %1}, %2;" : "=f"(lo), "=f"(hi) : "l"(v));
}
__device__ __forceinline__ u64t add2(u64t a, u64t b) {
    u64t d;
    asm("add.rn.f32x2 %0, %1, %2;" : "=l"(d) : "l"(a), "l"(b));
    return d;
}
__device__ __forceinline__ u64t fma2(u64t a, u64t b, u64t c) {
    u64t d;
    asm("fma.rn.f32x2 %0, %1, %2, %3;" : "=l"(d) : "l"(a), "l"(b), "l"(c));
    return d;
}
__device__ __forceinline__ u64t relu2(u64t x) {
    u64t r;
    asm("{\n\t"
        ".reg .f32 lo, hi;\n\t"
        "mov.b64 {lo, hi}, %1;\n\t"
        "max.f32 lo, lo, 0f00000000;\n\t"
        "max.f32 hi, hi, 0f00000000;\n\t"
        "mov.b64 %0, {lo, hi};\n\t"
        "}" : "=l"(r) : "l"(x));
    return r;
}

// ============================================================
// K1: gumbel softmax, 2 rows per block (ILP), float4 I/O
// ============================================================
__global__ void __launch_bounds__(256) gumbel_softmax_kernel(
    const float* __restrict__ u, const float* __restrict__ el,
    float* __restrict__ A)
{
    __shared__ float redm[2][8];
    __shared__ float reds[2][8];
    int t0 = blockIdx.x * 2;
    int tid = threadIdx.x;
    int s0 = tid * 4;

    float4 u4a = ((const float4*)(u + (size_t)t0 * Nn))[tid];
    float4 u4b = ((const float4*)(u + (size_t)(t0 + 1) * Nn))[tid];
    float4 e4a = ((const float4*)(el + (size_t)t0 * Nn))[tid];
    float4 e4b = ((const float4*)(el + (size_t)(t0 + 1) * Nn))[tid];

    float va[4], vb[4];
    {
        float ua[4] = {u4a.x, u4a.y, u4a.z, u4a.w};
        float ub[4] = {u4b.x, u4b.y, u4b.z, u4b.w};
        float ea[4] = {e4a.x, e4a.y, e4a.z, e4a.w};
        float eb[4] = {e4b.x, e4b.y, e4b.z, e4b.w};
#pragma unroll
        for (int i = 0; i < 4; i++) {
            float ga = -__logf(-__logf(ua[i] + 1e-9f) + 1e-9f);
            float gb = -__logf(-__logf(ub[i] + 1e-9f) + 1e-9f);
            float ma = (s0 + i == t0)     ? -1e9f : ea[i];
            float mb = (s0 + i == t0 + 1) ? -1e9f : eb[i];
            va[i] = (ma + ga) * 2.0f;   // / tau, tau = 0.5
            vb[i] = (mb + gb) * 2.0f;
        }
    }
    float mxa = fmaxf(fmaxf(va[0], va[1]), fmaxf(va[2], va[3]));
    float mxb = fmaxf(fmaxf(vb[0], vb[1]), fmaxf(vb[2], vb[3]));
#pragma unroll
    for (int o = 16; o; o >>= 1) {
        mxa = fmaxf(mxa, __shfl_xor_sync(0xffffffffu, mxa, o));
        mxb = fmaxf(mxb, __shfl_xor_sync(0xffffffffu, mxb, o));
    }
    if ((tid & 31) == 0) { redm[0][tid >> 5] = mxa; redm[1][tid >> 5] = mxb; }
    __syncthreads();
    float bma = redm[0][0], bmb = redm[1][0];
#pragma unroll
    for (int i = 1; i < 8; i++) {
        bma = fmaxf(bma, redm[0][i]);
        bmb = fmaxf(bmb, redm[1][i]);
    }

    float suma = 0.f, sumb = 0.f;
#pragma unroll
    for (int i = 0; i < 4; i++) {
        va[i] = __expf(va[i] - bma); suma += va[i];
        vb[i] = __expf(vb[i] - bmb); sumb += vb[i];
    }
#pragma unroll
    for (int o = 16; o; o >>= 1) {
        suma += __shfl_xor_sync(0xffffffffu, suma, o);
        sumb += __shfl_xor_sync(0xffffffffu, sumb, o);
    }
    if ((tid & 31) == 0) { reds[0][tid >> 5] = suma; reds[1][tid >> 5] = sumb; }
    __syncthreads();
    float bsa = reds[0][0], bsb = reds[1][0];
#pragma unroll
    for (int i = 1; i < 8; i++) { bsa += reds[0][i]; bsb += reds[1][i]; }
    float inva = 1.0f / bsa, invb = 1.0f / bsb;

    ((float4*)(A + (size_t)t0 * Nn))[tid] =
        make_float4(va[0] * inva, va[1] * inva, va[2] * inva, va[3] * inva);
    ((float4*)(A + (size_t)(t0 + 1) * Nn))[tid] =
        make_float4(vb[0] * invb, vb[1] * invb, vb[2] * invb, vb[3] * invb);
}

// ============================================================
// K2: chained in-smem GEMMs: proj = es@Wp+bp;  ps = proj@W1[:64],
//     ptb = proj@W1[64:]+b1.  128 blocks x 16 rows.
// ============================================================
__global__ void __launch_bounds__(256) pspt_kernel(
    const float* __restrict__ es, const float* __restrict__ Wp,
    const float* __restrict__ bp, const float* __restrict__ W1,
    const float* __restrict__ b1)
{
    __shared__ __align__(16) float sW1[128 * 64];  // 32 KB
    __shared__ __align__(16) float sWp[64 * 64];   // 16 KB
    __shared__ __align__(16) float sE[16 * 64];
    __shared__ __align__(16) float sPr[16 * 64];
    int tid = threadIdx.x;
    int row0 = blockIdx.x * 16;

    for (int i = tid; i < 8192; i += 256) sW1[i] = W1[i];
    for (int i = tid; i < 4096; i += 256) sWp[i] = Wp[i];
    for (int i = tid; i < 1024; i += 256) sE[i] = es[row0 * 64 + i];
    __syncthreads();

    int r = tid >> 4;
    int q = (tid & 15) << 2;
    {
        float4 acc = *(const float4*)(bp + q);
        const float* er = sE + r * 64;
#pragma unroll
        for (int k = 0; k < 64; k++) {
            float e = er[k];
            float4 w = *(const float4*)(sWp + k * 64 + q);
            acc.x = fmaf(e, w.x, acc.x);
            acc.y = fmaf(e, w.y, acc.y);
            acc.z = fmaf(e, w.z, acc.z);
            acc.w = fmaf(e, w.w, acc.w);
        }
        *(float4*)(sPr + r * 64 + q) = acc;
    }
    __syncthreads();
    {
        float4 aps = make_float4(0.f, 0.f, 0.f, 0.f);
        float4 apt = *(const float4*)(b1 + q);
        const float* pr = sPr + r * 64;
#pragma unroll
        for (int k = 0; k < 64; k++) {
            float p = pr[k];
            float4 wa = *(const float4*)(sW1 + k * 64 + q);
            float4 wb = *(const float4*)(sW1 + (64 + k) * 64 + q);
            aps.x = fmaf(p, wa.x, aps.x);
            aps.y = fmaf(p, wa.y, aps.y);
            aps.z = fmaf(p, wa.z, aps.z);
            aps.w = fmaf(p, wa.w, aps.w);
            apt.x = fmaf(p, wb.x, apt.x);
            apt.y = fmaf(p, wb.y, apt.y);
            apt.z = fmaf(p, wb.z, apt.z);
            apt.w = fmaf(p, wb.w, apt.w);
        }
        *(float4*)(g_ps  + (row0 + r) * 64 + q) = aps;
        *(float4*)(g_ptb + (row0 + r) * 64 + q) = apt;
    }
}

// ============================================================
// K3 (hot): hpart[c,b,t,:] = sum_{s in chunk c} A[t,s]*relu(ps[b,s,:]+ptb[b,t,:])
// grid (SCHUNKS, Nn/TT, Bn), 256 threads
// ============================================================
__global__ void __launch_bounds__(256, 4) msg_agg_kernel(const float* __restrict__ A)
{
    __shared__ __align__(16) float sP[SC * 64];          // 16 KB [s][d]
    __shared__ __align__(16) float sA[SC * SA_STRIDE];   // 17.4 KB [s][t], padded
    int b  = blockIdx.z;
    int t0 = blockIdx.y * TT;
    int s0 = blockIdx.x * SC;
    int tid = threadIdx.x;

    {
        const float4* gp = (const float4*)(g_ps + (b * Nn + s0) * Dn);
        float4* sp4 = (float4*)sP;
#pragma unroll
        for (int i = 0; i < (SC * 16) / 256; i++)
            sp4[tid + i * 256] = gp[tid + i * 256];
#pragma unroll
        for (int k = 0; k < (TT * SC) / 256; k++) {
            int i = tid + k * 256;
            int sl = i & (SC - 1);
            int tl = i >> 6;           // / SC(=64)
            sA[sl * SA_STRIDE + tl] = A[(t0 + tl) * Nn + s0 + sl];
        }
    }
    __syncthreads();

    int q4 = (tid & 15) << 2;
    int tg = tid >> 4;
    int ta = t0 + tg * 4;

    u64t c[8];
#pragma unroll
    for (int i = 0; i < 4; i++) {
        float4 cv = *(const float4*)(g_ptb + (b * Nn + ta + i) * Dn + q4);
        c[2 * i]     = pack2(cv.x, cv.y);
        c[2 * i + 1] = pack2(cv.z, cv.w);
    }
    u64t acc[8];
#pragma unroll
    for (int i = 0; i < 8; i++) acc[i] = 0;

    const float4* pbase = ((const float4*)sP) + (tid & 15);
    const float4* abase = ((const float4*)sA) + tg;

#pragma unroll 8
    for (int s = 0; s < SC; s++) {
        float4 p  = pbase[s * 16];
        float4 av = abase[s * (SA_STRIDE / 4)];
        u64t pa = pack2(p.x, p.y);
        u64t pb = pack2(p.z, p.w);
        u64t a0 = pack2(av.x, av.x);
        u64t a1 = pack2(av.y, av.y);
        u64t a2 = pack2(av.z, av.z);
        u64t a3 = pack2(av.w, av.w);
        acc[0] = fma2(a0, relu2(add2(pa, c[0])), acc[0]);
        acc[1] = fma2(a0, relu2(add2(pb, c[1])), acc[1]);
        acc[2] = fma2(a1, relu2(add2(pa, c[2])), acc[2]);
        acc[3] = fma2(a1, relu2(add2(pb, c[3])), acc[3]);
        acc[4] = fma2(a2, relu2(add2(pa, c[4])), acc[4]);
        acc[5] = fma2(a2, relu2(add2(pb, c[5])), acc[5]);
        acc[6] = fma2(a3, relu2(add2(pa, c[6])), acc[6]);
        acc[7] = fma2(a3, relu2(add2(pb, c[7])), acc[7]);
    }

    int cidx = blockIdx.x;
    float* hp = g_hpart + ((size_t)(cidx * Bn + b) * Nn + ta) * Dn + q4;
#pragma unroll
    for (int i = 0; i < 4; i++) {
        float4 o;
        unpack2(acc[2 * i],     o.x, o.y);
        unpack2(acc[2 * i + 1], o.z, o.w);
        *(float4*)(hp + (size_t)i * Dn) = o;
    }
}

// ============================================================
// K4: hbar = sum_c hpart;  next_state = es + hbar @ W2 + b2
// 256 blocks x 256 thr, 8 rows/block; 2 threads cooperate per work item
// ============================================================
__global__ void __launch_bounds__(256) out_kernel(
    const float* __restrict__ es, const float* __restrict__ W2,
    const float* __restrict__ b2, float* __restrict__ ns)
{
    __shared__ __align__(16) float sW[64 * 64];   // 16 KB
    __shared__ __align__(16) float sH[8 * 64];    // 2 KB
    int tid = threadIdx.x;
    int row0 = blockIdx.x * 8;     // global row in [0, B*N)
    int half = tid & 1;

    {
        float4* w4 = (float4*)sW;
        const float4* g4 = (const float4*)W2;
#pragma unroll
        for (int i = 0; i < 4; i++) w4[tid + i * 256] = g4[tid + i * 256];
    }

    // Phase A: 128 float4 items (8 rows x 16), 2 threads/item, 8 chunks each
    {
        int item = tid >> 1;                 // 0..127
        int r  = item >> 4;
        int f4 = item & 15;
        size_t base = ((size_t)(row0 + r)) * 16 + f4;
        float4 acc = make_float4(0.f, 0.f, 0.f, 0.f);
#pragma unroll
        for (int j = 0; j < 8; j++) {
            int cc = half * 8 + j;
            float4 v = ((const float4*)g_hpart)[(size_t)cc * (Bn * Nn * 16) + base];
            acc.x += v.x; acc.y += v.y; acc.z += v.z; acc.w += v.w;
        }
        acc.x += __shfl_xor_sync(0xffffffffu, acc.x, 1);
        acc.y += __shfl_xor_sync(0xffffffffu, acc.y, 1);
        acc.z += __shfl_xor_sync(0xffffffffu, acc.z, 1);
        acc.w += __shfl_xor_sync(0xffffffffu, acc.w, 1);
        if (!half) ((float4*)sH)[item] = acc;
    }
    __syncthreads();

    // Phase B: 128 outputs (8 rows x 16 float4), 2 threads/output, 32 k's each
    {
        int out = tid >> 1;                  // 0..127
        int r = out >> 4;
        int q = (out & 15) << 2;
        float4 acc = half ? make_float4(0.f, 0.f, 0.f, 0.f)
                          : *(const float4*)(b2 + q);
        const float* hr = sH + r * 64;
#pragma unroll
        for (int j = 0; j < 32; j++) {
            int k = half * 32 + j;
            float h = hr[k];
            float4 w = *(const float4*)(sW + k * 64 + q);
            acc.x = fmaf(h, w.x, acc.x);
            acc.y = fmaf(h, w.y, acc.y);
            acc.z = fmaf(h, w.z, acc.z);
            acc.w = fmaf(h, w.w, acc.w);
        }
        acc.x += __shfl_xor_sync(0xffffffffu, acc.x, 1);
        acc.y += __shfl_xor_sync(0xffffffffu, acc.y, 1);
        acc.z += __shfl_xor_sync(0xffffffffu, acc.z, 1);
        acc.w += __shfl_xor_sync(0xffffffffu, acc.w, 1);
        if (!half) {
            float4 e = *(const float4*)(es + ((size_t)(row0 + r)) * 64 + q);
            acc.x += e.x; acc.y += e.y; acc.z += e.z; acc.w += e.w;
            *(float4*)(ns + ((size_t)(row0 + r)) * 64 + q) = acc;
        }
    }
}

// ============================================================
extern "C" void kernel_launch(void* const* d_in, const int* in_sizes, int n_in,
                              void* d_out, int out_size)
{
    const float* es = (const float*)d_in[0];
    const float* u  = (const float*)d_in[1];
    const float* Wp = (const float*)d_in[2];
    const float* bp = (const float*)d_in[3];
    const float* el = (const float*)d_in[4];
    const float* W1 = (const float*)d_in[5];
    const float* b1 = (const float*)d_in[6];
    const float* W2 = (const float*)d_in[7];
    const float* b2 = (const float*)d_in[8];

    float* outNS = (float*)d_out;                 // next_state [B,N,D]
    float* outA  = outNS + Bn * Nn * Dn;          // A [N,N]

    gumbel_softmax_kernel<<<Nn / 2, 256>>>(u, el, outA);
    pspt_kernel<<<(Bn * Nn) / 16, 256>>>(es, Wp, bp, W1, b1);
    msg_agg_kernel<<<dim3(SCHUNKS, Nn / TT, Bn), 256>>>(outA);
    out_kernel<<<(Bn * Nn) / 8, 256>>>(es, W2, b2, outNS);
}